// round 3
// baseline (speedup 1.0000x reference)
#include <cuda_runtime.h>
#include <cuda_bf16.h>
#include <cstddef>

// ---------------- problem constants ----------------
constexpr int Kn   = 1024;           // RoI pairs
constexpr int Cc   = 128;            // channels
constexpr int Rr   = 7;              // roi size
constexpr int Dd   = Cc * Rr * Rr;   // 6272
constexpr int FFNn = 1024;
constexpr int GRP  = 4;
constexpr int CPG  = Cc / GRP;       // 32 input channels per group
constexpr int DYN  = Cc * CPG * 9;   // 36864 dyn-weight elems per sample
constexpr int Mb   = 64;             // boxes

// ---------------- scratch (no allocations allowed) ----------------
__device__ float g_v[(size_t)Kn * Dd];      // v, later reused as "flat"
__device__ float g_bufA[(size_t)Kn * Dd];   // pre-LN sums
__device__ float g_x[(size_t)Kn * Dd];      // post-LN1 spatial features
__device__ float g_gap[(size_t)Kn * Cc];
__device__ float g_dyn[(size_t)Kn * DYN];   // 151 MB dyn conv weights
__device__ float g_h[(size_t)Kn * FFNn];

// ============================================================
// Tiled SGEMM, "NT" layout: C[M,N] = A[M,K]·B[N,K]^T + bias[N]
// optional residual add (Res is M x N) and ReLU epilogue.
// Requires: M%128==0, N%128==0, K%16==0 (all shapes here satisfy this).
// ============================================================
template<bool RELU, bool ADDRES>
__global__ void __launch_bounds__(256, 2) sgemm_nt(
    const float* __restrict__ A, const float* __restrict__ B,
    const float* __restrict__ bias, const float* __restrict__ Res,
    float* __restrict__ C, int M, int N, int Kd)
{
    __shared__ float As[2][16][128];
    __shared__ float Bs[2][16][128];

    const int tid = threadIdx.x;
    const int m0 = blockIdx.y * 128;
    const int n0 = blockIdx.x * 128;

    // loaders: 128 rows x 16 k; each thread: rows lrow & lrow+64, one float4 each
    const int lrow = tid >> 2;        // 0..63
    const int lk   = (tid & 3) << 2;  // 0,4,8,12

    const float* Ap0 = A + (size_t)(m0 + lrow) * Kd + lk;
    const float* Ap1 = Ap0 + (size_t)64 * Kd;
    const float* Bp0 = B + (size_t)(n0 + lrow) * Kd + lk;
    const float* Bp1 = Bp0 + (size_t)64 * Kd;

    const int tx = tid & 15;   // 16 col groups of 8
    const int ty = tid >> 4;   // 16 row groups of 8

    float acc[8][8];
    #pragma unroll
    for (int i = 0; i < 8; i++)
        #pragma unroll
        for (int j = 0; j < 8; j++) acc[i][j] = 0.f;

    float4 a0 = *(const float4*)Ap0;
    float4 a1 = *(const float4*)Ap1;
    float4 b0 = *(const float4*)Bp0;
    float4 b1 = *(const float4*)Bp1;
    #pragma unroll
    for (int q = 0; q < 4; q++) {
        As[0][lk + q][lrow]      = ((const float*)&a0)[q];
        As[0][lk + q][lrow + 64] = ((const float*)&a1)[q];
        Bs[0][lk + q][lrow]      = ((const float*)&b0)[q];
        Bs[0][lk + q][lrow + 64] = ((const float*)&b1)[q];
    }
    __syncthreads();

    const int kTiles = Kd >> 4;
    int buf = 0;
    for (int kt = 0; kt < kTiles; ++kt) {
        if (kt + 1 < kTiles) {
            Ap0 += 16; Ap1 += 16; Bp0 += 16; Bp1 += 16;
            a0 = *(const float4*)Ap0;
            a1 = *(const float4*)Ap1;
            b0 = *(const float4*)Bp0;
            b1 = *(const float4*)Bp1;
        }
        #pragma unroll
        for (int kk = 0; kk < 16; ++kk) {
            float4 av0 = *(const float4*)&As[buf][kk][ty * 8];
            float4 av1 = *(const float4*)&As[buf][kk][ty * 8 + 4];
            float4 bv0 = *(const float4*)&Bs[buf][kk][tx * 8];
            float4 bv1 = *(const float4*)&Bs[buf][kk][tx * 8 + 4];
            float av[8] = {av0.x, av0.y, av0.z, av0.w, av1.x, av1.y, av1.z, av1.w};
            float bv[8] = {bv0.x, bv0.y, bv0.z, bv0.w, bv1.x, bv1.y, bv1.z, bv1.w};
            #pragma unroll
            for (int i = 0; i < 8; i++)
                #pragma unroll
                for (int j = 0; j < 8; j++)
                    acc[i][j] += av[i] * bv[j];
        }
        if (kt + 1 < kTiles) {
            buf ^= 1;
            #pragma unroll
            for (int q = 0; q < 4; q++) {
                As[buf][lk + q][lrow]      = ((const float*)&a0)[q];
                As[buf][lk + q][lrow + 64] = ((const float*)&a1)[q];
                Bs[buf][lk + q][lrow]      = ((const float*)&b0)[q];
                Bs[buf][lk + q][lrow + 64] = ((const float*)&b1)[q];
            }
            __syncthreads();
        }
    }

    // epilogue
    #pragma unroll
    for (int i = 0; i < 8; i++) {
        const size_t row = (size_t)(m0 + ty * 8 + i);
        float* crow = C + row * (size_t)N + n0 + tx * 8;
        const float* bp = bias + n0 + tx * 8;
        const float* rp = ADDRES ? (Res + row * (size_t)N + n0 + tx * 8) : nullptr;
        #pragma unroll
        for (int jj = 0; jj < 8; jj += 4) {
            float4 bb = *(const float4*)(bp + jj);
            float4 v;
            v.x = acc[i][jj + 0] + bb.x;
            v.y = acc[i][jj + 1] + bb.y;
            v.z = acc[i][jj + 2] + bb.z;
            v.w = acc[i][jj + 3] + bb.w;
            if (ADDRES) {
                float4 rr = *(const float4*)(rp + jj);
                v.x += rr.x; v.y += rr.y; v.z += rr.z; v.w += rr.w;
            }
            if (RELU) {
                v.x = fmaxf(v.x, 0.f); v.y = fmaxf(v.y, 0.f);
                v.z = fmaxf(v.z, 0.f); v.w = fmaxf(v.w, 0.f);
            }
            *(float4*)(crow + jj) = v;
        }
    }
}

// ============================================================
// LayerNorm over last Dd elems per row (handles LN1, LN2, LN3)
// ============================================================
__global__ void __launch_bounds__(256) ln_kernel(
    const float* __restrict__ in, const float* __restrict__ g,
    const float* __restrict__ b, float* __restrict__ out)
{
    const int row = blockIdx.x;
    const int t = threadIdx.x;
    const float4* p = (const float4*)(in + (size_t)row * Dd);

    float s = 0.f, s2 = 0.f;
    for (int i = t; i < Dd / 4; i += 256) {
        float4 v = p[i];
        s  += v.x + v.y + v.z + v.w;
        s2 += v.x * v.x + v.y * v.y + v.z * v.z + v.w * v.w;
    }
    #pragma unroll
    for (int o = 16; o > 0; o >>= 1) {
        s  += __shfl_xor_sync(0xffffffffu, s, o);
        s2 += __shfl_xor_sync(0xffffffffu, s2, o);
    }
    __shared__ float rs[8], rs2[8];
    __shared__ float smean, sinv;
    if ((t & 31) == 0) { rs[t >> 5] = s; rs2[t >> 5] = s2; }
    __syncthreads();
    if (t == 0) {
        float ts = 0.f, ts2 = 0.f;
        #pragma unroll
        for (int i = 0; i < 8; i++) { ts += rs[i]; ts2 += rs2[i]; }
        float mean = ts * (1.f / Dd);
        float var  = ts2 * (1.f / Dd) - mean * mean;
        smean = mean;
        sinv  = rsqrtf(var + 1e-5f);
    }
    __syncthreads();
    const float mean = smean, inv = sinv;
    const float4* g4 = (const float4*)g;
    const float4* b4 = (const float4*)b;
    float4* o4 = (float4*)(out + (size_t)row * Dd);
    for (int i = t; i < Dd / 4; i += 256) {
        float4 v = p[i], gg = g4[i], bb = b4[i], r;
        r.x = (v.x - mean) * inv * gg.x + bb.x;
        r.y = (v.y - mean) * inv * gg.y + bb.y;
        r.z = (v.z - mean) * inv * gg.z + bb.z;
        r.w = (v.w - mean) * inv * gg.w + bb.w;
        o4[i] = r;
    }
}

// ============================================================
// Global average pool over 7x7 per (sample, channel)
// ============================================================
__global__ void __launch_bounds__(128) gap_kernel(
    const float* __restrict__ x, float* __restrict__ gap)
{
    const int s = blockIdx.x;
    const int c = threadIdx.x;
    const float* p = x + ((size_t)s * Cc + c) * 49;
    float acc = 0.f;
    #pragma unroll
    for (int i = 0; i < 49; i++) acc += p[i];
    gap[(size_t)s * Cc + c] = acc * (1.f / 49.f);
}

// ============================================================
// Per-sample grouped dynamic 3x3 conv (SAME) + residual add.
// One block per sample, one thread per output channel.
// ============================================================
__global__ void __launch_bounds__(128) dynconv_kernel(
    const float* __restrict__ x, const float* __restrict__ dyn,
    float* __restrict__ out)
{
    const int s = blockIdx.x;
    const int t = threadIdx.x;          // = channel for load, = oc for compute
    __shared__ float sIn[Cc][81];       // zero-padded 9x9 per channel

    float* sc = sIn[t];
    #pragma unroll
    for (int i = 0; i < 81; i++) sc[i] = 0.f;
    const float* xp = x + ((size_t)s * Cc + t) * 49;
    #pragma unroll
    for (int y = 0; y < 7; y++)
        #pragma unroll
        for (int xx = 0; xx < 7; xx++)
            sc[(y + 1) * 9 + (xx + 1)] = xp[y * 7 + xx];
    __syncthreads();

    const int oc = t;
    const int grp = oc >> 5;                    // 32 out-ch per group
    const float* wbase = dyn + (size_t)s * DYN + (size_t)oc * (CPG * 9);
    const float* inbase = &sIn[grp * CPG][0];

    float acc[49];
    #pragma unroll
    for (int i = 0; i < 49; i++) acc[i] = 0.f;

    for (int ic = 0; ic < CPG; ic++) {
        const float* w = wbase + ic * 9;
        const float* in = inbase + ic * 81;
        const float w0 = w[0], w1 = w[1], w2 = w[2];
        const float w3 = w[3], w4 = w[4], w5 = w[5];
        const float w6 = w[6], w7 = w[7], w8 = w[8];
        #pragma unroll
        for (int y = 0; y < 7; y++) {
            float r0[9], r1[9], r2[9];
            #pragma unroll
            for (int j = 0; j < 9; j++) {
                r0[j] = in[y * 9 + j];
                r1[j] = in[(y + 1) * 9 + j];
                r2[j] = in[(y + 2) * 9 + j];
            }
            #pragma unroll
            for (int xx = 0; xx < 7; xx++) {
                float a = acc[y * 7 + xx];
                a += w0 * r0[xx] + w1 * r0[xx + 1] + w2 * r0[xx + 2];
                a += w3 * r1[xx] + w4 * r1[xx + 1] + w5 * r1[xx + 2];
                a += w6 * r2[xx] + w7 * r2[xx + 1] + w8 * r2[xx + 2];
                acc[y * 7 + xx] = a;
            }
        }
    }

    // residual: out = conv + spatial (read own channel back from smem interior)
    float* op = out + ((size_t)s * Cc + oc) * 49;
    const float* mysc = sIn[oc];
    #pragma unroll
    for (int y = 0; y < 7; y++)
        #pragma unroll
        for (int xx = 0; xx < 7; xx++)
            op[y * 7 + xx] = acc[y * 7 + xx] + mysc[(y + 1) * 9 + (xx + 1)];
}

// ============================================================
// Hungarian cost matrix: -iou + 0.5 * dist / max(dist.max(), 1)
// ============================================================
__global__ void __launch_bounds__(256) cost_kernel(
    const float* __restrict__ rb, const float* __restrict__ cb,
    float* __restrict__ out)
{
    __shared__ float sR[Mb * 4], sC[Mb * 4];
    __shared__ float sdist[Mb * Mb];
    __shared__ float rm[8];
    __shared__ float sMax;
    const int t = threadIdx.x;
    sR[t] = rb[t];
    sC[t] = cb[t];
    __syncthreads();

    float lm = 0.f;
    for (int idx = t; idx < Mb * Mb; idx += 256) {
        int i = idx >> 6, j = idx & 63;
        float rx = (sR[i * 4 + 0] + sR[i * 4 + 2]) * 0.5f;
        float ry = (sR[i * 4 + 1] + sR[i * 4 + 3]) * 0.5f;
        float cx = (sC[j * 4 + 0] + sC[j * 4 + 2]) * 0.5f;
        float cy = (sC[j * 4 + 1] + sC[j * 4 + 3]) * 0.5f;
        float d = fabsf(rx - cx) + fabsf(ry - cy);
        sdist[idx] = d;
        lm = fmaxf(lm, d);
    }
    #pragma unroll
    for (int o = 16; o > 0; o >>= 1) lm = fmaxf(lm, __shfl_xor_sync(0xffffffffu, lm, o));
    if ((t & 31) == 0) rm[t >> 5] = lm;
    __syncthreads();
    if (t == 0) {
        float m = 0.f;
        #pragma unroll
        for (int i = 0; i < 8; i++) m = fmaxf(m, rm[i]);
        sMax = fmaxf(m, 1.f);
    }
    __syncthreads();
    const float dmax = sMax;

    for (int idx = t; idx < Mb * Mb; idx += 256) {
        int i = idx >> 6, j = idx & 63;
        float ax0 = sR[i * 4 + 0], ay0 = sR[i * 4 + 1];
        float ax1 = sR[i * 4 + 2], ay1 = sR[i * 4 + 3];
        float bx0 = sC[j * 4 + 0], by0 = sC[j * 4 + 1];
        float bx1 = sC[j * 4 + 2], by1 = sC[j * 4 + 3];
        float areaA = (ax1 - ax0) * (ay1 - ay0);
        float areaB = (bx1 - bx0) * (by1 - by0);
        float lx = fmaxf(ax0, bx0), ly = fmaxf(ay0, by0);
        float rx = fminf(ax1, bx1), ry = fminf(ay1, by1);
        float w = fmaxf(rx - lx, 0.f), h = fmaxf(ry - ly, 0.f);
        float inter = w * h;
        float iou = inter / (areaA + areaB - inter);
        out[idx] = -1.0f * iou + 0.5f * sdist[idx] / dmax;
    }
}

// ============================================================
// host launcher
// ============================================================
extern "C" void kernel_launch(void* const* d_in, const int* in_sizes, int n_in,
                              void* d_out, int out_size)
{
    const float* wf      = (const float*)d_in[0];   // wrong_features (K,C,R,R)
    const float* rf      = (const float*)d_in[1];   // right_features
    const float* refb    = (const float*)d_in[2];
    const float* curb    = (const float*)d_in[3];
    // d_in[4..7] = wq,bq,wk,bk : mathematically dead (softmax over 1 key == 1)
    const float* wv      = (const float*)d_in[8];
    const float* bv      = (const float*)d_in[9];
    const float* wo      = (const float*)d_in[10];
    const float* bo      = (const float*)d_in[11];
    const float* g1      = (const float*)d_in[12];
    const float* b1      = (const float*)d_in[13];
    const float* wgen_w  = (const float*)d_in[14];
    const float* wgen_b  = (const float*)d_in[15];
    const float* g2      = (const float*)d_in[16];
    const float* b2      = (const float*)d_in[17];
    const float* wf1     = (const float*)d_in[18];
    const float* bf1     = (const float*)d_in[19];
    const float* wf2     = (const float*)d_in[20];
    const float* bf2     = (const float*)d_in[21];
    const float* g3      = (const float*)d_in[22];
    const float* b3      = (const float*)d_in[23];
    float* out = (float*)d_out;

    float *v, *bufA, *x, *gap, *dyn, *h;
    cudaGetSymbolAddress((void**)&v,    g_v);
    cudaGetSymbolAddress((void**)&bufA, g_bufA);
    cudaGetSymbolAddress((void**)&x,    g_x);
    cudaGetSymbolAddress((void**)&gap,  g_gap);
    cudaGetSymbolAddress((void**)&dyn,  g_dyn);
    cudaGetSymbolAddress((void**)&h,    g_h);

    // 1. v = rf @ wv^T + bv          (softmax==1 => attn == v)
    sgemm_nt<false, false><<<dim3(Dd / 128, Kn / 128), 256>>>(
        rf, wv, bv, nullptr, v, Kn, Dd, Dd);
    // 2. pre1 = v @ wo^T + bo + wf
    sgemm_nt<false, true><<<dim3(Dd / 128, Kn / 128), 256>>>(
        v, wo, bo, wf, bufA, Kn, Dd, Dd);
    // 3. x = LN(pre1)
    ln_kernel<<<Kn, 256>>>(bufA, g1, b1, x);
    // 4. gap
    gap_kernel<<<Kn, 128>>>(x, gap);
    // 5. dyn weights = gap @ wgen^T + wgen_b
    sgemm_nt<false, false><<<dim3(DYN / 128, Kn / 128), 256>>>(
        gap, wgen_w, wgen_b, nullptr, dyn, Kn, DYN, Cc);
    // 6. bufA = dynconv(x) + x
    dynconv_kernel<<<Kn, 128>>>(x, dyn, bufA);
    // 7. flat = LN(bufA)  (reuse v buffer)
    ln_kernel<<<Kn, 256>>>(bufA, g2, b2, v);
    // 8. h = relu(flat @ wf1^T + bf1)
    sgemm_nt<true, false><<<dim3(FFNn / 128, Kn / 128), 256>>>(
        v, wf1, bf1, nullptr, h, Kn, FFNn, Dd);
    // 9. bufA = h @ wf2^T + bf2 + flat
    sgemm_nt<false, true><<<dim3(Dd / 128, Kn / 128), 256>>>(
        h, wf2, bf2, v, bufA, Kn, Dd, FFNn);
    // 10. out aggregated = LN(bufA)
    ln_kernel<<<Kn, 256>>>(bufA, g3, b3, out);
    // 11. cost matrix
    cost_kernel<<<1, 256>>>(refb, curb, out + (size_t)Kn * Dd);
}

// round 5
// speedup vs baseline: 2.7539x; 2.7539x over previous
#include <cuda_runtime.h>
#include <cuda_bf16.h>
#include <cstdint>
#include <cstddef>

constexpr int Kn = 1024, Cc = 128, Dd = 6272, FFNn = 1024, CPG = 32, DYN = 36864, Mb = 64;

// ---------------- scratch (no allocations allowed) ----------------
__device__ __align__(128) float g_v   [(size_t)Kn * Dd];
__device__ __align__(128) float g_bufA[(size_t)Kn * Dd];
__device__ __align__(128) float g_x   [(size_t)Kn * Dd];
__device__ __align__(128) float g_flat[(size_t)Kn * Dd];
__device__ __align__(128) float g_gap [(size_t)Kn * Cc];
__device__ __align__(128) float g_dyn [(size_t)Kn * DYN];
__device__ __align__(128) float g_h   [(size_t)Kn * FFNn];

// ---------------- PTX helpers ----------------
__device__ __forceinline__ uint32_t f2tf(float x) {
    uint32_t r;
    asm("cvt.rna.tf32.f32 %0, %1;" : "=r"(r) : "f"(x));
    return r;
}
__device__ __forceinline__ void mma_tf32(float* c, const uint32_t* a, const uint32_t* b) {
    asm volatile(
        "mma.sync.aligned.m16n8k8.row.col.f32.tf32.tf32.f32 "
        "{%0,%1,%2,%3}, {%4,%5,%6,%7}, {%8,%9}, {%0,%1,%2,%3};"
        : "+f"(c[0]), "+f"(c[1]), "+f"(c[2]), "+f"(c[3])
        : "r"(a[0]), "r"(a[1]), "r"(a[2]), "r"(a[3]), "r"(b[0]), "r"(b[1]));
}
#define CP_A16(dst, src) \
    asm volatile("cp.async.ca.shared.global [%0], [%1], 16;" :: "r"(dst), "l"(src) : "memory")
#define CP_COMMIT() asm volatile("cp.async.commit_group;" ::: "memory")
#define CP_WAIT1()  asm volatile("cp.async.wait_group 1;" ::: "memory")

// ============================================================
// tf32 tensor-core GEMM: C[M,N] = A[M,K]·B[N,K]^T + bias (+Res) (ReLU)
// block 128x128x16, 8 warps (32m x 64n each), 3-stage cp.async pipeline.
// smem rows padded to 20 floats -> all fragment LDS bank-conflict-free.
// ============================================================
constexpr int SROW = 20;                   // floats per padded 16-float row
constexpr int STAGE_F = 2 * 128 * SROW;    // floats per stage (A+B) = 5120
constexpr int GEMM_SMEM = 3 * STAGE_F * 4; // 61440 bytes

template<bool RELU, bool ADDRES>
__global__ void __launch_bounds__(256, 2) gemm_tf32(
    const float* __restrict__ A, const float* __restrict__ B,
    const float* __restrict__ bias, const float* __restrict__ Res,
    float* __restrict__ C, int N, int Kd)
{
    extern __shared__ float sm[];
    const int tid = threadIdx.x;
    const int wid = tid >> 5, lane = tid & 31;
    const int lr = lane >> 2, lc = lane & 3;
    const int m0 = blockIdx.x * 128, n0 = blockIdx.y * 128;
    const int wrow = (wid >> 1) * 32, wcol = (wid & 1) * 64;
    const int kTiles = Kd >> 4;

    const uint32_t smem_base = (uint32_t)__cvta_generic_to_shared(sm);

    // per-thread load coords: two 16B chunks for A, two for B per stage
    const int c0r = tid >> 2, c0q = tid & 3;          // chunk tid
    const int c1r = (tid + 256) >> 2, c1q = tid & 3;  // chunk tid+256 (same q)

    const float* Abase = A + (size_t)m0 * Kd;
    const float* Bbase = B + (size_t)n0 * Kd;

    auto load_stage = [&](int s, int kt) {
        const uint32_t base = smem_base + (uint32_t)s * (STAGE_F * 4);
        const int ko = kt * 16;
        CP_A16(base + (uint32_t)(c0r * SROW + c0q * 4) * 4,          Abase + (size_t)c0r * Kd + ko + c0q * 4);
        CP_A16(base + (uint32_t)(c1r * SROW + c1q * 4) * 4,          Abase + (size_t)c1r * Kd + ko + c1q * 4);
        CP_A16(base + (uint32_t)(128 * SROW + c0r * SROW + c0q * 4) * 4, Bbase + (size_t)c0r * Kd + ko + c0q * 4);
        CP_A16(base + (uint32_t)(128 * SROW + c1r * SROW + c1q * 4) * 4, Bbase + (size_t)c1r * Kd + ko + c1q * 4);
    };

    float acc[2][8][4];
    #pragma unroll
    for (int mt = 0; mt < 2; mt++)
        #pragma unroll
        for (int nt = 0; nt < 8; nt++)
            #pragma unroll
            for (int q = 0; q < 4; q++) acc[mt][nt][q] = 0.f;

    load_stage(0, 0); CP_COMMIT();
    load_stage(1, 1); CP_COMMIT();

    for (int kt = 0; kt < kTiles; ++kt) {
        CP_WAIT1();
        __syncthreads();
        const int nx = kt + 2;
        if (nx < kTiles) load_stage(nx % 3, nx);
        CP_COMMIT();

        const float* As = sm + (kt % 3) * STAGE_F;
        const float* Bs = As + 128 * SROW;
        #pragma unroll
        for (int kk = 0; kk < 2; kk++) {
            const int kb = kk * 8;
            uint32_t a[2][4], b[8][2];
            #pragma unroll
            for (int mt = 0; mt < 2; mt++) {
                const int r = wrow + mt * 16 + lr;
                a[mt][0] = f2tf(As[r * SROW + kb + lc]);
                a[mt][1] = f2tf(As[(r + 8) * SROW + kb + lc]);
                a[mt][2] = f2tf(As[r * SROW + kb + lc + 4]);
                a[mt][3] = f2tf(As[(r + 8) * SROW + kb + lc + 4]);
            }
            #pragma unroll
            for (int nt = 0; nt < 8; nt++) {
                const int n = wcol + nt * 8 + lr;
                b[nt][0] = f2tf(Bs[n * SROW + kb + lc]);
                b[nt][1] = f2tf(Bs[n * SROW + kb + lc + 4]);
            }
            #pragma unroll
            for (int mt = 0; mt < 2; mt++)
                #pragma unroll
                for (int nt = 0; nt < 8; nt++)
                    mma_tf32(acc[mt][nt], a[mt], b[nt]);
        }
    }

    // epilogue: c0,c1 -> (row, col..col+1), c2,c3 -> (row+8, col..col+1)
    #pragma unroll
    for (int mt = 0; mt < 2; mt++) {
        #pragma unroll
        for (int nt = 0; nt < 8; nt++) {
            const int row0 = m0 + wrow + mt * 16 + lr;
            const int col  = n0 + wcol + nt * 8 + 2 * lc;
            const float b0 = bias[col], b1 = bias[col + 1];
            float v0 = acc[mt][nt][0] + b0, v1 = acc[mt][nt][1] + b1;
            float v2 = acc[mt][nt][2] + b0, v3 = acc[mt][nt][3] + b1;
            if (ADDRES) {
                float2 r0 = *(const float2*)(Res + (size_t)row0 * N + col);
                float2 r1 = *(const float2*)(Res + (size_t)(row0 + 8) * N + col);
                v0 += r0.x; v1 += r0.y; v2 += r1.x; v3 += r1.y;
            }
            if (RELU) {
                v0 = fmaxf(v0, 0.f); v1 = fmaxf(v1, 0.f);
                v2 = fmaxf(v2, 0.f); v3 = fmaxf(v3, 0.f);
            }
            *(float2*)(C + (size_t)row0 * N + col)       = make_float2(v0, v1);
            *(float2*)(C + (size_t)(row0 + 8) * N + col) = make_float2(v2, v3);
        }
    }
}

// ============================================================
// LayerNorm over Dd per row
// ============================================================
__global__ void __launch_bounds__(256) ln_kernel(
    const float* __restrict__ in, const float* __restrict__ g,
    const float* __restrict__ b, float* __restrict__ out)
{
    const int row = blockIdx.x, t = threadIdx.x;
    const float4* p = (const float4*)(in + (size_t)row * Dd);
    float s = 0.f, s2 = 0.f;
    for (int i = t; i < Dd / 4; i += 256) {
        float4 v = p[i];
        s += v.x + v.y + v.z + v.w;
        s2 += v.x * v.x + v.y * v.y + v.z * v.z + v.w * v.w;
    }
    #pragma unroll
    for (int o = 16; o > 0; o >>= 1) {
        s  += __shfl_xor_sync(~0u, s, o);
        s2 += __shfl_xor_sync(~0u, s2, o);
    }
    __shared__ float rs[8], rs2[8], smean, sinv;
    if ((t & 31) == 0) { rs[t >> 5] = s; rs2[t >> 5] = s2; }
    __syncthreads();
    if (t == 0) {
        float ts = 0.f, ts2 = 0.f;
        #pragma unroll
        for (int i = 0; i < 8; i++) { ts += rs[i]; ts2 += rs2[i]; }
        float mean = ts * (1.f / Dd);
        smean = mean;
        sinv = rsqrtf(ts2 * (1.f / Dd) - mean * mean + 1e-5f);
    }
    __syncthreads();
    const float mean = smean, inv = sinv;
    const float4 *g4 = (const float4*)g, *b4 = (const float4*)b;
    float4* o4 = (float4*)(out + (size_t)row * Dd);
    for (int i = t; i < Dd / 4; i += 256) {
        float4 v = p[i], gg = g4[i], bb = b4[i], r;
        r.x = (v.x - mean) * inv * gg.x + bb.x;
        r.y = (v.y - mean) * inv * gg.y + bb.y;
        r.z = (v.z - mean) * inv * gg.z + bb.z;
        r.w = (v.w - mean) * inv * gg.w + bb.w;
        o4[i] = r;
    }
}

__global__ void __launch_bounds__(128) gap_kernel(
    const float* __restrict__ x, float* __restrict__ gap)
{
    const float* p = x + ((size_t)blockIdx.x * Cc + threadIdx.x) * 49;
    float a = 0.f;
    #pragma unroll
    for (int i = 0; i < 49; i++) a += p[i];
    gap[(size_t)blockIdx.x * Cc + threadIdx.x] = a * (1.f / 49.f);
}

// ============================================================
// Per-sample grouped dynamic 3x3 conv + residual
// ============================================================
__global__ void __launch_bounds__(128) dynconv_kernel(
    const float* __restrict__ x, const float* __restrict__ dyn,
    float* __restrict__ out)
{
    const int s = blockIdx.x, t = threadIdx.x;
    __shared__ float sIn[Cc][81];
    float* sc = sIn[t];
    #pragma unroll
    for (int i = 0; i < 81; i++) sc[i] = 0.f;
    const float* xp = x + ((size_t)s * Cc + t) * 49;
    #pragma unroll
    for (int y = 0; y < 7; y++)
        #pragma unroll
        for (int xx = 0; xx < 7; xx++)
            sc[(y + 1) * 9 + xx + 1] = xp[y * 7 + xx];
    __syncthreads();

    const int grp = t >> 5;
    const float* wb = dyn + (size_t)s * DYN + (size_t)t * (CPG * 9);
    const float* ib = &sIn[grp * CPG][0];
    float acc[49];
    #pragma unroll
    for (int i = 0; i < 49; i++) acc[i] = 0.f;
    for (int ic = 0; ic < CPG; ic++) {
        const float* w = wb + ic * 9;
        const float* in = ib + ic * 81;
        float w0 = w[0], w1 = w[1], w2 = w[2], w3 = w[3], w4 = w[4];
        float w5 = w[5], w6 = w[6], w7 = w[7], w8 = w[8];
        #pragma unroll
        for (int y = 0; y < 7; y++) {
            #pragma unroll
            for (int xx = 0; xx < 7; xx++) {
                float a = acc[y * 7 + xx];
                a += w0 * in[y * 9 + xx]       + w1 * in[y * 9 + xx + 1]       + w2 * in[y * 9 + xx + 2];
                a += w3 * in[(y + 1) * 9 + xx] + w4 * in[(y + 1) * 9 + xx + 1] + w5 * in[(y + 1) * 9 + xx + 2];
                a += w6 * in[(y + 2) * 9 + xx] + w7 * in[(y + 2) * 9 + xx + 1] + w8 * in[(y + 2) * 9 + xx + 2];
                acc[y * 7 + xx] = a;
            }
        }
    }
    float* op = out + ((size_t)s * Cc + t) * 49;
    const float* ms = sIn[t];
    #pragma unroll
    for (int y = 0; y < 7; y++)
        #pragma unroll
        for (int xx = 0; xx < 7; xx++)
            op[y * 7 + xx] = acc[y * 7 + xx] + ms[(y + 1) * 9 + xx + 1];
}

// ============================================================
// cost matrix
// ============================================================
__global__ void __launch_bounds__(256) cost_kernel(
    const float* __restrict__ rb, const float* __restrict__ cb, float* __restrict__ out)
{
    __shared__ float sR[Mb * 4], sC[Mb * 4], sdist[Mb * Mb], rm[8], sMax;
    const int t = threadIdx.x;
    sR[t] = rb[t]; sC[t] = cb[t];
    __syncthreads();
    float lm = 0.f;
    for (int idx = t; idx < Mb * Mb; idx += 256) {
        int i = idx >> 6, j = idx & 63;
        float d = fabsf((sR[i * 4] + sR[i * 4 + 2]) * 0.5f - (sC[j * 4] + sC[j * 4 + 2]) * 0.5f)
                + fabsf((sR[i * 4 + 1] + sR[i * 4 + 3]) * 0.5f - (sC[j * 4 + 1] + sC[j * 4 + 3]) * 0.5f);
        sdist[idx] = d;
        lm = fmaxf(lm, d);
    }
    #pragma unroll
    for (int o = 16; o > 0; o >>= 1) lm = fmaxf(lm, __shfl_xor_sync(~0u, lm, o));
    if ((t & 31) == 0) rm[t >> 5] = lm;
    __syncthreads();
    if (t == 0) {
        float m = 0.f;
        #pragma unroll
        for (int i = 0; i < 8; i++) m = fmaxf(m, rm[i]);
        sMax = fmaxf(m, 1.f);
    }
    __syncthreads();
    const float dmax = sMax;
    for (int idx = t; idx < Mb * Mb; idx += 256) {
        int i = idx >> 6, j = idx & 63;
        float ax0 = sR[i*4], ay0 = sR[i*4+1], ax1 = sR[i*4+2], ay1 = sR[i*4+3];
        float bx0 = sC[j*4], by0 = sC[j*4+1], bx1 = sC[j*4+2], by1 = sC[j*4+3];
        float areaA = (ax1 - ax0) * (ay1 - ay0), areaB = (bx1 - bx0) * (by1 - by0);
        float w = fmaxf(fminf(ax1, bx1) - fmaxf(ax0, bx0), 0.f);
        float h = fmaxf(fminf(ay1, by1) - fmaxf(ay0, by0), 0.f);
        float inter = w * h;
        out[idx] = -inter / (areaA + areaB - inter) + 0.5f * sdist[idx] / dmax;
    }
}

// ============================================================
// host launcher
// ============================================================
extern "C" void kernel_launch(void* const* d_in, const int* in_sizes, int n_in,
                              void* d_out, int out_size)
{
    const float* wf     = (const float*)d_in[0];
    const float* rf     = (const float*)d_in[1];
    const float* refb   = (const float*)d_in[2];
    const float* curb   = (const float*)d_in[3];
    // d_in[4..7] = wq,bq,wk,bk: dead (softmax over one key == 1 -> attn == v)
    const float* wv     = (const float*)d_in[8];
    const float* bv     = (const float*)d_in[9];
    const float* wo     = (const float*)d_in[10];
    const float* bo     = (const float*)d_in[11];
    const float* g1     = (const float*)d_in[12];
    const float* b1     = (const float*)d_in[13];
    const float* wgen_w = (const float*)d_in[14];
    const float* wgen_b = (const float*)d_in[15];
    const float* g2     = (const float*)d_in[16];
    const float* b2     = (const float*)d_in[17];
    const float* wf1    = (const float*)d_in[18];
    const float* bf1    = (const float*)d_in[19];
    const float* wf2    = (const float*)d_in[20];
    const float* bf2    = (const float*)d_in[21];
    const float* g3     = (const float*)d_in[22];
    const float* b3     = (const float*)d_in[23];
    float* out = (float*)d_out;

    float *v, *bufA, *x, *flat, *gap, *dyn, *h;
    cudaGetSymbolAddress((void**)&v, g_v);       cudaGetSymbolAddress((void**)&bufA, g_bufA);
    cudaGetSymbolAddress((void**)&x, g_x);       cudaGetSymbolAddress((void**)&flat, g_flat);
    cudaGetSymbolAddress((void**)&gap, g_gap);   cudaGetSymbolAddress((void**)&dyn, g_dyn);
    cudaGetSymbolAddress((void**)&h, g_h);

    cudaFuncSetAttribute(gemm_tf32<false, false>, cudaFuncAttributeMaxDynamicSharedMemorySize, GEMM_SMEM);
    cudaFuncSetAttribute(gemm_tf32<false, true>,  cudaFuncAttributeMaxDynamicSharedMemorySize, GEMM_SMEM);
    cudaFuncSetAttribute(gemm_tf32<true, false>,  cudaFuncAttributeMaxDynamicSharedMemorySize, GEMM_SMEM);

    // 1. v = rf @ wv^T + bv
    gemm_tf32<false, false><<<dim3(8, 49), 256, GEMM_SMEM>>>(rf, wv, bv, nullptr, v, Dd, Dd);
    // 2. bufA = v @ wo^T + bo + wf
    gemm_tf32<false, true><<<dim3(8, 49), 256, GEMM_SMEM>>>(v, wo, bo, wf, bufA, Dd, Dd);
    // 3. x = LN(bufA)
    ln_kernel<<<Kn, 256>>>(bufA, g1, b1, x);
    // 4. gap
    gap_kernel<<<Kn, 128>>>(x, gap);
    // 5. dyn = gap @ wgen^T + wgen_b
    gemm_tf32<false, false><<<dim3(8, 288), 256, GEMM_SMEM>>>(gap, wgen_w, wgen_b, nullptr, dyn, DYN, Cc);
    // 6. bufA = dynconv(x) + x
    dynconv_kernel<<<Kn, 128>>>(x, dyn, bufA);
    // 7. flat = LN(bufA)
    ln_kernel<<<Kn, 256>>>(bufA, g2, b2, flat);
    // 8. h = relu(flat @ wf1^T + bf1)
    gemm_tf32<true, false><<<dim3(8, 8), 256, GEMM_SMEM>>>(flat, wf1, bf1, nullptr, h, FFNn, Dd);
    // 9. bufA = h @ wf2^T + bf2 + flat
    gemm_tf32<false, true><<<dim3(8, 49), 256, GEMM_SMEM>>>(h, wf2, bf2, flat, bufA, Dd, FFNn);
    // 10. out = LN(bufA)
    ln_kernel<<<Kn, 256>>>(bufA, g3, b3, out);
    // 11. cost matrix
    cost_kernel<<<1, 256>>>(refb, curb, out + (size_t)Kn * Dd);
}